// round 8
// baseline (speedup 1.0000x reference)
#include <cuda_runtime.h>
#include <cuda_bf16.h>
#include <math.h>
#include <stdint.h>

// ---------------------------------------------------------------------------
// Problem constants
// ---------------------------------------------------------------------------
#define BATCH     2
#define NQ        10000
#define MTOT      21760
#define EMBED     256
#define HEADS     8
#define HEAD_DIM  32
#define LEVELS    4
#define POINTS    4
#define COMBOS    (HEADS*LEVELS*POINTS)
#define KDIM      256

__device__ __constant__ int c_shape[LEVELS]  = {128, 64, 32, 16};
__device__ __constant__ int c_start[LEVELS]  = {0, 16384, 20480, 21504};

// ---------------------------------------------------------------------------
// Device scratch
// ---------------------------------------------------------------------------
__device__ float g_v[BATCH * MTOT * EMBED];
__device__ float g_off[BATCH * NQ * (COMBOS*2)];
__device__ float g_attn[BATCH * NQ * COMBOS];

__device__ __nv_bfloat16 g_val_hi[BATCH * MTOT * KDIM];
__device__ __nv_bfloat16 g_val_lo[BATCH * MTOT * KDIM];
__device__ __nv_bfloat16 g_q_hi[BATCH * NQ * KDIM];
__device__ __nv_bfloat16 g_q_lo[BATCH * NQ * KDIM];
__device__ __nv_bfloat16 g_wv_hi[256 * KDIM],  g_wv_lo[256 * KDIM];
__device__ __nv_bfloat16 g_wo_hi[256 * KDIM],  g_wo_lo[256 * KDIM];
__device__ __nv_bfloat16 g_wa_hi[128 * KDIM],  g_wa_lo[128 * KDIM];

// ---------------------------------------------------------------------------
// PTX wrappers (baseline sm_80+ features; safe under plain sm_103 PTX target)
// ---------------------------------------------------------------------------
__device__ __forceinline__ uint32_t smem_u32(const void* p) {
    uint32_t a;
    asm("{ .reg .u64 t; cvta.to.shared.u64 t, %1; cvt.u32.u64 %0, t; }" : "=r"(a) : "l"(p));
    return a;
}
__device__ __forceinline__ void ldsm4(uint32_t* r, uint32_t addr) {
    asm volatile("ldmatrix.sync.aligned.m8n8.x4.shared.b16 {%0,%1,%2,%3}, [%4];"
        : "=r"(r[0]), "=r"(r[1]), "=r"(r[2]), "=r"(r[3]) : "r"(addr));
}
__device__ __forceinline__ void mma_bf16(float* c, const uint32_t* a, const uint32_t* b) {
    asm volatile("mma.sync.aligned.m16n8k16.row.col.f32.bf16.bf16.f32 "
        "{%0,%1,%2,%3}, {%4,%5,%6,%7}, {%8,%9}, {%0,%1,%2,%3};"
        : "+f"(c[0]), "+f"(c[1]), "+f"(c[2]), "+f"(c[3])
        : "r"(a[0]), "r"(a[1]), "r"(a[2]), "r"(a[3]), "r"(b[0]), "r"(b[1]));
}
__device__ __forceinline__ void cpa16(uint32_t dst, const void* src, uint32_t sz) {
    asm volatile("cp.async.ca.shared.global [%0], [%1], 16, %2;" :: "r"(dst), "l"(src), "r"(sz));
}
#define CPA_COMMIT()  asm volatile("cp.async.commit_group;" ::: "memory")
#define CPA_WAIT1()   asm volatile("cp.async.wait_group 1;" ::: "memory")
#define CPA_WAIT0()   asm volatile("cp.async.wait_group 0;" ::: "memory")

// ---------------------------------------------------------------------------
// Prep: fused fp32->bf16 hi/lo splits for value+query (one launch)
// ---------------------------------------------------------------------------
__device__ __forceinline__ void split4(const float* in, __nv_bfloat16* hi,
                                       __nv_bfloat16* lo, int i) {
    float4 a = ((const float4*)in)[i];
    __nv_bfloat16 h[4], l[4];
    float v[4] = {a.x, a.y, a.z, a.w};
#pragma unroll
    for (int j = 0; j < 4; j++) {
        h[j] = __float2bfloat16(v[j]);
        l[j] = __float2bfloat16(v[j] - __bfloat162float(h[j]));
    }
    ((uint2*)hi)[i] = *(uint2*)h;
    ((uint2*)lo)[i] = *(uint2*)l;
}

__global__ void split_all(const float* __restrict__ value, const float* __restrict__ query,
                          __nv_bfloat16* __restrict__ vh, __nv_bfloat16* __restrict__ vl,
                          __nv_bfloat16* __restrict__ qh, __nv_bfloat16* __restrict__ ql,
                          int nv4, int nq4)
{
    int i = blockIdx.x * blockDim.x + threadIdx.x;
    if (i < nv4)            split4(value, vh, vl, i);
    else if (i < nv4 + nq4) split4(query, qh, ql, i - nv4);
}

// Fused transpose+split of all three weight matrices (one launch).
__global__ void prep_weights(const float* __restrict__ Wv, const float* __restrict__ Wo,
                             const float* __restrict__ Wa,
                             __nv_bfloat16* __restrict__ vh, __nv_bfloat16* __restrict__ vl,
                             __nv_bfloat16* __restrict__ oh, __nv_bfloat16* __restrict__ ol,
                             __nv_bfloat16* __restrict__ ah, __nv_bfloat16* __restrict__ al)
{
    int idx = blockIdx.x * blockDim.x + threadIdx.x;   // 0 .. 163839
    const float* W; __nv_bfloat16 *hi, *lo; int Nin, local;
    if (idx < 65536)        { W = Wv; hi = vh; lo = vl; Nin = 256; local = idx; }
    else if (idx < 131072)  { W = Wo; hi = oh; lo = ol; Nin = 256; local = idx - 65536; }
    else if (idx < 163840)  { W = Wa; hi = ah; lo = al; Nin = 128; local = idx - 131072; }
    else return;
    int n = local >> 8;
    int k = local & 255;
    float v = W[k * Nin + n];
    __nv_bfloat16 h = __float2bfloat16(v);
    hi[local] = h;
    lo[local] = __float2bfloat16(v - __bfloat162float(h));
}

// ---------------------------------------------------------------------------
// HMMA GEMM v2:  C[M,N] = A[M,256] * Bt[N,256]^T + bias
// CTA tile 128x128, BK=64, cp.async double-buffered. 256 thr (8 warps, 4m x 2n).
// bf16 hi/lo 3-term split.
// smem/stage (64KB): [A_hi 16K][A_lo 16K][B_hi 16K][B_lo 16K]; 2 stages = 128KB.
// ---------------------------------------------------------------------------
#define STG   65536
#define OAL   16384
#define OBH   32768
#define OBL   49152
#define SM_TOTAL (2*STG)

__device__ __forceinline__ uint32_t sw128(int row, int ch) {   // row<128, ch<8 (16B chunks)
    return (uint32_t)row * 128u + (uint32_t)((ch ^ (row & 7)) << 4);
}

__global__ __launch_bounds__(256) void gemm_hmma2(
    const __nv_bfloat16* __restrict__ Ahi, const __nv_bfloat16* __restrict__ Alo,
    const __nv_bfloat16* __restrict__ Bhi, const __nv_bfloat16* __restrict__ Blo,
    const float* __restrict__ bias, float* __restrict__ C, int M, int N)
{
    extern __shared__ char smem[];
    const uint32_t sb = smem_u32(smem);
    const int tid  = threadIdx.x;
    const int wid  = tid >> 5;
    const int lane = tid & 31;
    const int wm   = wid & 3;        // 4 m-groups of 32 rows
    const int wn   = wid >> 2;       // 2 n-groups of 64 cols
    const int row0 = blockIdx.y * 128;
    const int col0 = blockIdx.x * 128;

    float acc[2][8][4];
#pragma unroll
    for (int a = 0; a < 2; a++)
#pragma unroll
        for (int b = 0; b < 8; b++)
#pragma unroll
            for (int f = 0; f < 4; f++) acc[a][b][f] = 0.f;

    // ---- async stage loader: 1024 16B-chunks per sub-tile, 4 per thread ----
#define LOAD_STAGE(stbase, k0)                                                  \
    do {                                                                        \
        _Pragma("unroll")                                                       \
        for (int i = 0; i < 4; i++) {                                           \
            int c   = tid + i * 256;                                            \
            int row = c >> 3;                                                   \
            int ch  = c & 7;                                                    \
            uint32_t sw = sw128(row, ch);                                       \
            int gr = row0 + row;                                                \
            uint32_t sz = (gr < M) ? 16u : 0u;                                  \
            size_t ga = (size_t)(gr < M ? gr : 0) * 256 + (k0) + ch * 8;        \
            cpa16(sb + (stbase) + sw,        Ahi + ga, sz);                     \
            cpa16(sb + (stbase) + OAL + sw,  Alo + ga, sz);                     \
            size_t gb = (size_t)(col0 + row) * 256 + (k0) + ch * 8;             \
            cpa16(sb + (stbase) + OBH + sw,  Bhi + gb, 16u);                    \
            cpa16(sb + (stbase) + OBL + sw,  Blo + gb, 16u);                    \
        }                                                                       \
    } while (0)

    LOAD_STAGE(0, 0);
    CPA_COMMIT();

#pragma unroll
    for (int cc = 0; cc < 4; cc++) {
        const uint32_t st = (uint32_t)(cc & 1) * STG;
        if (cc < 3) {
            LOAD_STAGE((uint32_t)((cc + 1) & 1) * STG, (cc + 1) * 64);
            CPA_COMMIT();
            CPA_WAIT1();
        } else {
            CPA_WAIT0();
        }
        __syncthreads();

        // ---- compute this 64-wide K chunk: 4 k16-steps ----
#pragma unroll
        for (int ks = 0; ks < 4; ks++) {
            uint32_t ah[2][4], al[2][4];
#pragma unroll
            for (int tm = 0; tm < 2; tm++) {
                int rA = wm * 32 + tm * 16 + (lane & 15);
                int ch = 2 * ks + (lane >> 4);
                uint32_t ad = sb + st + sw128(rA, ch);
                ldsm4(ah[tm], ad);
                ldsm4(al[tm], ad + OAL);
            }
#pragma unroll
            for (int g = 0; g < 4; g++) {
                int rB  = wn * 64 + g * 16 + ((lane >> 4) & 1) * 8 + (lane & 7);
                int chb = 2 * ks + ((lane >> 3) & 1);
                uint32_t bd = sb + st + OBH + sw128(rB, chb);
                uint32_t bh[4], bl[4];
                ldsm4(bh, bd);
                ldsm4(bl, bd + (OBL - OBH));
#pragma unroll
                for (int tm = 0; tm < 2; tm++) {
                    mma_bf16(acc[tm][2*g],   ah[tm], bh);       // hi*hi
                    mma_bf16(acc[tm][2*g],   ah[tm], bl);       // hi*lo
                    mma_bf16(acc[tm][2*g],   al[tm], bh);       // lo*hi
                    mma_bf16(acc[tm][2*g+1], ah[tm], bh + 2);
                    mma_bf16(acc[tm][2*g+1], ah[tm], bl + 2);
                    mma_bf16(acc[tm][2*g+1], al[tm], bh + 2);
                }
            }
        }
        __syncthreads();
    }

    // ---- epilogue: bias + store ----
    const int row_in = lane >> 2;
    const int col_in = 2 * (lane & 3);
#pragma unroll
    for (int tm = 0; tm < 2; tm++) {
        const int gr0 = row0 + wm * 32 + tm * 16 + row_in;
#pragma unroll
        for (int j = 0; j < 8; j++) {
            const int gcol = col0 + wn * 64 + j * 8 + col_in;
            const float bx = bias[gcol];
            const float by = bias[gcol + 1];
            if (gr0 < M) {
                float2 o = make_float2(acc[tm][j][0] + bx, acc[tm][j][1] + by);
                *(float2*)&C[(size_t)gr0 * N + gcol] = o;
            }
            if (gr0 + 8 < M) {
                float2 o = make_float2(acc[tm][j][2] + bx, acc[tm][j][3] + by);
                *(float2*)&C[(size_t)(gr0 + 8) * N + gcol] = o;
            }
        }
    }
#undef LOAD_STAGE
}

// ---------------------------------------------------------------------------
// Sampler (unchanged — gather-bound at ~91us)
// ---------------------------------------------------------------------------
#define QPB 2

__global__ __launch_bounds__(256) void deform_sample(
    const float* __restrict__ ref_points, float* __restrict__ out)
{
    __shared__ float4 s_w[QPB * COMBOS];
    __shared__ int4   s_i[QPB * COMBOS];

    const int t = threadIdx.x;
    {
        const int q    = t >> 7;
        const int c    = t & 127;
        const int head = c >> 4;
        const int i16  = c & 15;
        const int lv   = i16 >> 2;
        const int bn   = blockIdx.x * QPB + q;
        const int b    = bn / NQ;

        float lg = g_attn[(size_t)bn * COMBOS + c];
        float mx = lg;
#pragma unroll
        for (int s = 8; s >= 1; s >>= 1)
            mx = fmaxf(mx, __shfl_xor_sync(0xffffffffu, mx, s));
        float e = __expf(lg - mx);
        float ssum = e;
#pragma unroll
        for (int s = 8; s >= 1; s >>= 1)
            ssum += __shfl_xor_sync(0xffffffffu, ssum, s);
        const float aw = e / ssum;

        const float2 od = ((const float2*)g_off)[(size_t)bn * COMBOS + c];
        const float rx = ref_points[bn * 2 + 0];
        const float ry = ref_points[bn * 2 + 1];

        const int   S  = c_shape[lv];
        const float fS = (float)S;
        const float x = (rx + od.x / fS) * fS - 0.5f;
        const float y = (ry + od.y / fS) * fS - 0.5f;
        const float x0f = floorf(x), y0f = floorf(y);
        const float lx = x - x0f, ly = y - y0f;
        const int x0 = (int)x0f, y0 = (int)y0f;
        const int x1 = x0 + 1,   y1 = y0 + 1;

        const bool vx0 = ((unsigned)x0 < (unsigned)S);
        const bool vx1 = ((unsigned)x1 < (unsigned)S);
        const bool vy0 = ((unsigned)y0 < (unsigned)S);
        const bool vy1 = ((unsigned)y1 < (unsigned)S);

        const int xc0 = min(max(x0, 0), S - 1);
        const int xc1 = min(max(x1, 0), S - 1);
        const int yc0 = min(max(y0, 0), S - 1);
        const int yc1 = min(max(y1, 0), S - 1);

        float4 wv;
        wv.x = (vx0 && vy0) ? (1.f - lx) * (1.f - ly) * aw : 0.f;
        wv.y = (vx1 && vy0) ? lx * (1.f - ly) * aw : 0.f;
        wv.z = (vx0 && vy1) ? (1.f - lx) * ly * aw : 0.f;
        wv.w = (vx1 && vy1) ? lx * ly * aw : 0.f;

        const int base = b * MTOT + c_start[lv];
        const int hoff = head * HEAD_DIM;
        int4 iv;
        iv.x = (base + yc0 * S + xc0) * EMBED + hoff;
        iv.y = (base + yc0 * S + xc1) * EMBED + hoff;
        iv.z = (base + yc1 * S + xc0) * EMBED + hoff;
        iv.w = (base + yc1 * S + xc1) * EMBED + hoff;

        s_w[t] = wv;
        s_i[t] = iv;
    }
    __syncthreads();

    const int head = t >> 5;
    const int lane = t & 31;
#pragma unroll
    for (int q = 0; q < QPB; q++) {
        const int bn   = blockIdx.x * QPB + q;
        const int slot = q * COMBOS + head * (LEVELS * POINTS);
        float acc = 0.0f;
#pragma unroll
        for (int i = 0; i < LEVELS * POINTS; i++) {
            const float4 wv = s_w[slot + i];
            const int4   iv = s_i[slot + i];
            float v0 = __ldg(&g_v[iv.x + lane]);
            float v1 = __ldg(&g_v[iv.y + lane]);
            float v2 = __ldg(&g_v[iv.z + lane]);
            float v3 = __ldg(&g_v[iv.w + lane]);
            acc = fmaf(wv.x, v0, acc);
            acc = fmaf(wv.y, v1, acc);
            acc = fmaf(wv.z, v2, acc);
            acc = fmaf(wv.w, v3, acc);
        }
        out[(size_t)bn * EMBED + head * HEAD_DIM + lane] = acc;
    }
}

// ---------------------------------------------------------------------------
// Launch
// ---------------------------------------------------------------------------
extern "C" void kernel_launch(void* const* d_in, const int* in_sizes, int n_in,
                              void* d_out, int out_size)
{
    const float* query  = (const float*)d_in[0];
    const float* value  = (const float*)d_in[2];
    const float* refpts = (const float*)d_in[3];
    const float* W_off  = (const float*)d_in[6];
    const float* b_off  = (const float*)d_in[7];
    const float* W_attn = (const float*)d_in[8];
    const float* b_attn = (const float*)d_in[9];
    const float* W_v    = (const float*)d_in[10];
    const float* b_v    = (const float*)d_in[11];
    float* out = (float*)d_out;

    void *pv, *poff, *pattn;
    void *pvh, *pvl, *pqh, *pql;
    void *pwvh, *pwvl, *pwoh, *pwol, *pwah, *pwal;
    cudaGetSymbolAddress(&pv, g_v);
    cudaGetSymbolAddress(&poff, g_off);
    cudaGetSymbolAddress(&pattn, g_attn);
    cudaGetSymbolAddress(&pvh, g_val_hi);  cudaGetSymbolAddress(&pvl, g_val_lo);
    cudaGetSymbolAddress(&pqh, g_q_hi);    cudaGetSymbolAddress(&pql, g_q_lo);
    cudaGetSymbolAddress(&pwvh, g_wv_hi);  cudaGetSymbolAddress(&pwvl, g_wv_lo);
    cudaGetSymbolAddress(&pwoh, g_wo_hi);  cudaGetSymbolAddress(&pwol, g_wo_lo);
    cudaGetSymbolAddress(&pwah, g_wa_hi);  cudaGetSymbolAddress(&pwal, g_wa_lo);

    const int MV = BATCH * MTOT;   // 43520
    const int MQ = BATCH * NQ;     // 20000

    cudaFuncSetAttribute(gemm_hmma2, cudaFuncAttributeMaxDynamicSharedMemorySize, SM_TOTAL);

    // prep (2 launches)
    {
        int nv4 = MV * KDIM / 4, nq4 = MQ * KDIM / 4;
        int tot = nv4 + nq4;
        split_all<<<(tot + 255) / 256, 256>>>(value, query,
            (__nv_bfloat16*)pvh, (__nv_bfloat16*)pvl,
            (__nv_bfloat16*)pqh, (__nv_bfloat16*)pql, nv4, nq4);
    }
    prep_weights<<<(163840 + 255) / 256, 256>>>(W_v, W_off, W_attn,
        (__nv_bfloat16*)pwvh, (__nv_bfloat16*)pwvl,
        (__nv_bfloat16*)pwoh, (__nv_bfloat16*)pwol,
        (__nv_bfloat16*)pwah, (__nv_bfloat16*)pwal);

    // GEMMs
    {
        dim3 grid(2, (MV + 127) / 128);   // N=256
        gemm_hmma2<<<grid, 256, SM_TOTAL>>>((const __nv_bfloat16*)pvh, (const __nv_bfloat16*)pvl,
                                            (const __nv_bfloat16*)pwvh, (const __nv_bfloat16*)pwvl,
                                            b_v, (float*)pv, MV, 256);
    }
    {
        dim3 grid(2, (MQ + 127) / 128);   // N=256
        gemm_hmma2<<<grid, 256, SM_TOTAL>>>((const __nv_bfloat16*)pqh, (const __nv_bfloat16*)pql,
                                            (const __nv_bfloat16*)pwoh, (const __nv_bfloat16*)pwol,
                                            b_off, (float*)poff, MQ, 256);
    }
    {
        dim3 grid(1, (MQ + 127) / 128);   // N=128
        gemm_hmma2<<<grid, 256, SM_TOTAL>>>((const __nv_bfloat16*)pqh, (const __nv_bfloat16*)pql,
                                            (const __nv_bfloat16*)pwah, (const __nv_bfloat16*)pwal,
                                            b_attn, (float*)pattn, MQ, 128);
    }

    // sampler
    deform_sample<<<(BATCH * NQ) / QPB, 256>>>(refpts, out);
}

// round 9
// speedup vs baseline: 1.0500x; 1.0500x over previous
#include <cuda_runtime.h>
#include <cuda_bf16.h>
#include <cuda_fp16.h>
#include <math.h>
#include <stdint.h>

// ---------------------------------------------------------------------------
// Problem constants
// ---------------------------------------------------------------------------
#define BATCH     2
#define NQ        10000
#define MTOT      21760
#define EMBED     256
#define HEADS     8
#define HEAD_DIM  32
#define LEVELS    4
#define POINTS    4
#define COMBOS    (HEADS*LEVELS*POINTS)
#define KDIM      256
#define NQC       384            // combined off(256) + attn(128) output width

__device__ __constant__ int c_shape[LEVELS]  = {128, 64, 32, 16};
__device__ __constant__ int c_start[LEVELS]  = {0, 16384, 20480, 21504};

// ---------------------------------------------------------------------------
// Device scratch
// ---------------------------------------------------------------------------
__device__ __half g_vh[BATCH * MTOT * EMBED];          // projected value, fp16
__device__ float  g_qc[BATCH * NQ * NQC];              // [off(256) | attn(128)]

__device__ __nv_bfloat16 g_val_hi[BATCH * MTOT * KDIM];
__device__ __nv_bfloat16 g_val_lo[BATCH * MTOT * KDIM];
__device__ __nv_bfloat16 g_q_hi[BATCH * NQ * KDIM];
__device__ __nv_bfloat16 g_q_lo[BATCH * NQ * KDIM];
__device__ __nv_bfloat16 g_wv_hi[256 * KDIM],  g_wv_lo[256 * KDIM];
__device__ __nv_bfloat16 g_wq_hi[NQC * KDIM],  g_wq_lo[NQC * KDIM];
__device__ float g_bq[NQC];

// ---------------------------------------------------------------------------
// PTX wrappers (baseline sm_80+ features; safe under plain sm_103 PTX target)
// ---------------------------------------------------------------------------
__device__ __forceinline__ uint32_t smem_u32(const void* p) {
    uint32_t a;
    asm("{ .reg .u64 t; cvta.to.shared.u64 t, %1; cvt.u32.u64 %0, t; }" : "=r"(a) : "l"(p));
    return a;
}
__device__ __forceinline__ void ldsm4(uint32_t* r, uint32_t addr) {
    asm volatile("ldmatrix.sync.aligned.m8n8.x4.shared.b16 {%0,%1,%2,%3}, [%4];"
        : "=r"(r[0]), "=r"(r[1]), "=r"(r[2]), "=r"(r[3]) : "r"(addr));
}
__device__ __forceinline__ void mma_bf16(float* c, const uint32_t* a, const uint32_t* b) {
    asm volatile("mma.sync.aligned.m16n8k16.row.col.f32.bf16.bf16.f32 "
        "{%0,%1,%2,%3}, {%4,%5,%6,%7}, {%8,%9}, {%0,%1,%2,%3};"
        : "+f"(c[0]), "+f"(c[1]), "+f"(c[2]), "+f"(c[3])
        : "r"(a[0]), "r"(a[1]), "r"(a[2]), "r"(a[3]), "r"(b[0]), "r"(b[1]));
}
__device__ __forceinline__ void cpa16(uint32_t dst, const void* src, uint32_t sz) {
    asm volatile("cp.async.ca.shared.global [%0], [%1], 16, %2;" :: "r"(dst), "l"(src), "r"(sz));
}
#define CPA_COMMIT()  asm volatile("cp.async.commit_group;" ::: "memory")
#define CPA_WAIT1()   asm volatile("cp.async.wait_group 1;" ::: "memory")
#define CPA_WAIT0()   asm volatile("cp.async.wait_group 0;" ::: "memory")

// ---------------------------------------------------------------------------
// ONE prep kernel: activation splits + weight transposes + bias concat
// ---------------------------------------------------------------------------
__device__ __forceinline__ void split4(const float* in, __nv_bfloat16* hi,
                                       __nv_bfloat16* lo, int i) {
    float4 a = ((const float4*)in)[i];
    __nv_bfloat16 h[4], l[4];
    float v[4] = {a.x, a.y, a.z, a.w};
#pragma unroll
    for (int j = 0; j < 4; j++) {
        h[j] = __float2bfloat16(v[j]);
        l[j] = __float2bfloat16(v[j] - __bfloat162float(h[j]));
    }
    ((uint2*)hi)[i] = *(uint2*)h;
    ((uint2*)lo)[i] = *(uint2*)l;
}

#define NV4 (BATCH * MTOT * KDIM / 4)     // 2785280
#define NQ4 (BATCH * NQ * KDIM / 4)       // 1280000
#define NWV (256 * KDIM)                  // 65536
#define NWQ (NQC * KDIM)                  // 98304
#define PREP_TOT (NV4 + NQ4 + NWV + NWQ + NQC)

__global__ void prep_all(const float* __restrict__ value, const float* __restrict__ query,
                         const float* __restrict__ Wv, const float* __restrict__ Wo,
                         const float* __restrict__ Wa,
                         const float* __restrict__ b_off, const float* __restrict__ b_attn)
{
    int i = blockIdx.x * blockDim.x + threadIdx.x;
    if (i < NV4) { split4(value, g_val_hi, g_val_lo, i); return; }
    i -= NV4;
    if (i < NQ4) { split4(query, g_q_hi, g_q_lo, i); return; }
    i -= NQ4;
    if (i < NWV) {   // W_v transpose+split -> g_wv rows [0,256)
        int n = i >> 8, k = i & 255;
        float v = Wv[k * 256 + n];
        __nv_bfloat16 h = __float2bfloat16(v);
        g_wv_hi[i] = h;
        g_wv_lo[i] = __float2bfloat16(v - __bfloat162float(h));
        return;
    }
    i -= NWV;
    if (i < NWQ) {   // combined q-weights: rows [0,256)=W_off, [256,384)=W_attn
        int n = i >> 8, k = i & 255;
        float v = (n < 256) ? Wo[k * 256 + n] : Wa[k * 128 + (n - 256)];
        __nv_bfloat16 h = __float2bfloat16(v);
        g_wq_hi[i] = h;
        g_wq_lo[i] = __float2bfloat16(v - __bfloat162float(h));
        return;
    }
    i -= NWQ;
    if (i < NQC) g_bq[i] = (i < 256) ? b_off[i] : b_attn[i - 256];
}

// ---------------------------------------------------------------------------
// HMMA GEMM:  C[M,N] = A[M,256] * Bt[N,256]^T + bias
// CTA tile 128x128, BK=64, cp.async double-buffered, 8 warps (4m x 2n).
// bf16 hi/lo 3-term split. Output: fp32 (Cf) or fp16 (Ch) — exactly one non-null.
// ---------------------------------------------------------------------------
#define STG   65536
#define OAL   16384
#define OBH   32768
#define OBL   49152
#define SM_TOTAL (2*STG)

__device__ __forceinline__ uint32_t sw128(int row, int ch) {
    return (uint32_t)row * 128u + (uint32_t)((ch ^ (row & 7)) << 4);
}

__global__ __launch_bounds__(256) void gemm_hmma2(
    const __nv_bfloat16* __restrict__ Ahi, const __nv_bfloat16* __restrict__ Alo,
    const __nv_bfloat16* __restrict__ Bhi, const __nv_bfloat16* __restrict__ Blo,
    const float* __restrict__ bias, float* __restrict__ Cf, __half* __restrict__ Ch,
    int M, int N)
{
    extern __shared__ char smem[];
    const uint32_t sb = smem_u32(smem);
    const int tid  = threadIdx.x;
    const int wid  = tid >> 5;
    const int lane = tid & 31;
    const int wm   = wid & 3;
    const int wn   = wid >> 2;
    const int row0 = blockIdx.y * 128;
    const int col0 = blockIdx.x * 128;

    float acc[2][8][4];
#pragma unroll
    for (int a = 0; a < 2; a++)
#pragma unroll
        for (int b = 0; b < 8; b++)
#pragma unroll
            for (int f = 0; f < 4; f++) acc[a][b][f] = 0.f;

#define LOAD_STAGE(stbase, k0)                                                  \
    do {                                                                        \
        _Pragma("unroll")                                                       \
        for (int i = 0; i < 4; i++) {                                           \
            int c   = tid + i * 256;                                            \
            int row = c >> 3;                                                   \
            int ch  = c & 7;                                                    \
            uint32_t sw = sw128(row, ch);                                       \
            int gr = row0 + row;                                                \
            uint32_t sz = (gr < M) ? 16u : 0u;                                  \
            size_t ga = (size_t)(gr < M ? gr : 0) * 256 + (k0) + ch * 8;        \
            cpa16(sb + (stbase) + sw,        Ahi + ga, sz);                     \
            cpa16(sb + (stbase) + OAL + sw,  Alo + ga, sz);                     \
            size_t gb = (size_t)(col0 + row) * 256 + (k0) + ch * 8;             \
            cpa16(sb + (stbase) + OBH + sw,  Bhi + gb, 16u);                    \
            cpa16(sb + (stbase) + OBL + sw,  Blo + gb, 16u);                    \
        }                                                                       \
    } while (0)

    LOAD_STAGE(0, 0);
    CPA_COMMIT();

#pragma unroll
    for (int cc = 0; cc < 4; cc++) {
        const uint32_t st = (uint32_t)(cc & 1) * STG;
        if (cc < 3) {
            LOAD_STAGE((uint32_t)((cc + 1) & 1) * STG, (cc + 1) * 64);
            CPA_COMMIT();
            CPA_WAIT1();
        } else {
            CPA_WAIT0();
        }
        __syncthreads();

#pragma unroll
        for (int ks = 0; ks < 4; ks++) {
            uint32_t ah[2][4], al[2][4];
#pragma unroll
            for (int tm = 0; tm < 2; tm++) {
                int rA = wm * 32 + tm * 16 + (lane & 15);
                int ch = 2 * ks + (lane >> 4);
                uint32_t ad = sb + st + sw128(rA, ch);
                ldsm4(ah[tm], ad);
                ldsm4(al[tm], ad + OAL);
            }
#pragma unroll
            for (int g = 0; g < 4; g++) {
                int rB  = wn * 64 + g * 16 + ((lane >> 4) & 1) * 8 + (lane & 7);
                int chb = 2 * ks + ((lane >> 3) & 1);
                uint32_t bd = sb + st + OBH + sw128(rB, chb);
                uint32_t bh[4], bl[4];
                ldsm4(bh, bd);
                ldsm4(bl, bd + (OBL - OBH));
#pragma unroll
                for (int tm = 0; tm < 2; tm++) {
                    mma_bf16(acc[tm][2*g],   ah[tm], bh);
                    mma_bf16(acc[tm][2*g],   ah[tm], bl);
                    mma_bf16(acc[tm][2*g],   al[tm], bh);
                    mma_bf16(acc[tm][2*g+1], ah[tm], bh + 2);
                    mma_bf16(acc[tm][2*g+1], ah[tm], bl + 2);
                    mma_bf16(acc[tm][2*g+1], al[tm], bh + 2);
                }
            }
        }
        __syncthreads();
    }

    // epilogue: bias + store (fp32 or fp16)
    const int row_in = lane >> 2;
    const int col_in = 2 * (lane & 3);
#pragma unroll
    for (int tm = 0; tm < 2; tm++) {
        const int gr0 = row0 + wm * 32 + tm * 16 + row_in;
#pragma unroll
        for (int j = 0; j < 8; j++) {
            const int gcol = col0 + wn * 64 + j * 8 + col_in;
            const float bx = bias[gcol];
            const float by = bias[gcol + 1];
            if (Ch) {
                if (gr0 < M)
                    *(__half2*)&Ch[(size_t)gr0 * N + gcol] =
                        __floats2half2_rn(acc[tm][j][0] + bx, acc[tm][j][1] + by);
                if (gr0 + 8 < M)
                    *(__half2*)&Ch[(size_t)(gr0 + 8) * N + gcol] =
                        __floats2half2_rn(acc[tm][j][2] + bx, acc[tm][j][3] + by);
            } else {
                if (gr0 < M)
                    *(float2*)&Cf[(size_t)gr0 * N + gcol] =
                        make_float2(acc[tm][j][0] + bx, acc[tm][j][1] + by);
                if (gr0 + 8 < M)
                    *(float2*)&Cf[(size_t)(gr0 + 8) * N + gcol] =
                        make_float2(acc[tm][j][2] + bx, acc[tm][j][3] + by);
            }
        }
    }
#undef LOAD_STAGE
}

// ---------------------------------------------------------------------------
// Sampler: two-phase, fp16 gathers
// ---------------------------------------------------------------------------
#define QPB 2

__global__ __launch_bounds__(256) void deform_sample(
    const float* __restrict__ ref_points, float* __restrict__ out)
{
    __shared__ float4 s_w[QPB * COMBOS];
    __shared__ int4   s_i[QPB * COMBOS];

    const int t = threadIdx.x;
    {
        const int q    = t >> 7;
        const int c    = t & 127;
        const int head = c >> 4;
        const int i16  = c & 15;
        const int lv   = i16 >> 2;
        const int bn   = blockIdx.x * QPB + q;
        const int b    = bn / NQ;

        // logits live in g_qc columns [256, 384)
        float lg = g_qc[(size_t)bn * NQC + 256 + c];
        float mx = lg;
#pragma unroll
        for (int s = 8; s >= 1; s >>= 1)
            mx = fmaxf(mx, __shfl_xor_sync(0xffffffffu, mx, s));
        float e = __expf(lg - mx);
        float ssum = e;
#pragma unroll
        for (int s = 8; s >= 1; s >>= 1)
            ssum += __shfl_xor_sync(0xffffffffu, ssum, s);
        const float aw = e / ssum;

        // offsets live in g_qc columns [0, 256): (2c, 2c+1)
        const float2 od = *(const float2*)&g_qc[(size_t)bn * NQC + 2 * c];
        const float rx = ref_points[bn * 2 + 0];
        const float ry = ref_points[bn * 2 + 1];

        const int   S  = c_shape[lv];
        const float fS = (float)S;
        const float x = (rx + od.x / fS) * fS - 0.5f;
        const float y = (ry + od.y / fS) * fS - 0.5f;
        const float x0f = floorf(x), y0f = floorf(y);
        const float lx = x - x0f, ly = y - y0f;
        const int x0 = (int)x0f, y0 = (int)y0f;
        const int x1 = x0 + 1,   y1 = y0 + 1;

        const bool vx0 = ((unsigned)x0 < (unsigned)S);
        const bool vx1 = ((unsigned)x1 < (unsigned)S);
        const bool vy0 = ((unsigned)y0 < (unsigned)S);
        const bool vy1 = ((unsigned)y1 < (unsigned)S);

        const int xc0 = min(max(x0, 0), S - 1);
        const int xc1 = min(max(x1, 0), S - 1);
        const int yc0 = min(max(y0, 0), S - 1);
        const int yc1 = min(max(y1, 0), S - 1);

        float4 wv;
        wv.x = (vx0 && vy0) ? (1.f - lx) * (1.f - ly) * aw : 0.f;
        wv.y = (vx1 && vy0) ? lx * (1.f - ly) * aw : 0.f;
        wv.z = (vx0 && vy1) ? (1.f - lx) * ly * aw : 0.f;
        wv.w = (vx1 && vy1) ? lx * ly * aw : 0.f;

        const int base = b * MTOT + c_start[lv];
        const int hoff = head * HEAD_DIM;
        int4 iv;
        iv.x = (base + yc0 * S + xc0) * EMBED + hoff;
        iv.y = (base + yc0 * S + xc1) * EMBED + hoff;
        iv.z = (base + yc1 * S + xc0) * EMBED + hoff;
        iv.w = (base + yc1 * S + xc1) * EMBED + hoff;

        s_w[t] = wv;
        s_i[t] = iv;
    }
    __syncthreads();

    const int head = t >> 5;
    const int lane = t & 31;
#pragma unroll
    for (int q = 0; q < QPB; q++) {
        const int bn   = blockIdx.x * QPB + q;
        const int slot = q * COMBOS + head * (LEVELS * POINTS);
        float acc = 0.0f;
#pragma unroll
        for (int i = 0; i < LEVELS * POINTS; i++) {
            const float4 wv = s_w[slot + i];
            const int4   iv = s_i[slot + i];
            float v0 = __half2float(__ldg(&g_vh[iv.x + lane]));
            float v1 = __half2float(__ldg(&g_vh[iv.y + lane]));
            float v2 = __half2float(__ldg(&g_vh[iv.z + lane]));
            float v3 = __half2float(__ldg(&g_vh[iv.w + lane]));
            acc = fmaf(wv.x, v0, acc);
            acc = fmaf(wv.y, v1, acc);
            acc = fmaf(wv.z, v2, acc);
            acc = fmaf(wv.w, v3, acc);
        }
        out[(size_t)bn * EMBED + head * HEAD_DIM + lane] = acc;
    }
}

// ---------------------------------------------------------------------------
// Launch: 4 kernels total
// ---------------------------------------------------------------------------
extern "C" void kernel_launch(void* const* d_in, const int* in_sizes, int n_in,
                              void* d_out, int out_size)
{
    const float* query  = (const float*)d_in[0];
    const float* value  = (const float*)d_in[2];
    const float* refpts = (const float*)d_in[3];
    const float* W_off  = (const float*)d_in[6];
    const float* b_off  = (const float*)d_in[7];
    const float* W_attn = (const float*)d_in[8];
    const float* b_attn = (const float*)d_in[9];
    const float* W_v    = (const float*)d_in[10];
    const float* b_v    = (const float*)d_in[11];
    float* out = (float*)d_out;

    void *pvh16, *pqc, *pbq;
    void *pvh, *pvl, *pqh, *pql, *pwvh, *pwvl, *pwqh, *pwql;
    cudaGetSymbolAddress(&pvh16, g_vh);
    cudaGetSymbolAddress(&pqc,   g_qc);
    cudaGetSymbolAddress(&pbq,   g_bq);
    cudaGetSymbolAddress(&pvh, g_val_hi);  cudaGetSymbolAddress(&pvl, g_val_lo);
    cudaGetSymbolAddress(&pqh, g_q_hi);    cudaGetSymbolAddress(&pql, g_q_lo);
    cudaGetSymbolAddress(&pwvh, g_wv_hi);  cudaGetSymbolAddress(&pwvl, g_wv_lo);
    cudaGetSymbolAddress(&pwqh, g_wq_hi);  cudaGetSymbolAddress(&pwql, g_wq_lo);

    const int MV = BATCH * MTOT;   // 43520
    const int MQ = BATCH * NQ;     // 20000

    cudaFuncSetAttribute(gemm_hmma2, cudaFuncAttributeMaxDynamicSharedMemorySize, SM_TOTAL);

    // 1) all prep in one launch
    prep_all<<<(PREP_TOT + 255) / 256, 256>>>(value, query, W_v, W_off, W_attn,
                                              b_off, b_attn);

    // 2) v GEMM -> fp16 output
    {
        dim3 grid(2, (MV + 127) / 128);   // N=256
        gemm_hmma2<<<grid, 256, SM_TOTAL>>>((const __nv_bfloat16*)pvh, (const __nv_bfloat16*)pvl,
                                            (const __nv_bfloat16*)pwvh, (const __nv_bfloat16*)pwvl,
                                            b_v, nullptr, (__half*)pvh16, MV, 256);
    }
    // 3) combined off+attn GEMM -> fp32 g_qc
    {
        dim3 grid(3, (MQ + 127) / 128);   // N=384
        gemm_hmma2<<<grid, 256, SM_TOTAL>>>((const __nv_bfloat16*)pqh, (const __nv_bfloat16*)pql,
                                            (const __nv_bfloat16*)pwqh, (const __nv_bfloat16*)pwql,
                                            (const float*)pbq, (float*)pqc, nullptr, MQ, NQC);
    }
    // 4) sampler
    deform_sample<<<(BATCH * NQ) / QPB, 256>>>(refpts, out);
}